// round 2
// baseline (speedup 1.0000x reference)
#include <cuda_runtime.h>
#include <cuda_bf16.h>
#include <math.h>

// BlockSparseAttention: B=2,H=16,S=2048,D=128, block=128, NB=16
// Per-(i,j)-block independent softmax; out_i = sum_{j active} softmax(Q_i K_j^T * scale) V_j
//
// Round 1: fix mask dtype. The harness may deliver block_mask as uint8 bools,
// int32, or float32 0/1. A prekernel sniffs the byte pattern (safe: reads only
// the first 256 bytes, valid under every candidate dtype) and normalizes into
// a __device__ int array. Main compute unchanged from Round 0 fp32 baseline.

#define B_  2
#define H_  16
#define S_  2048
#define D_  128
#define BS_ 128
#define NB_ 16
#define PAD 129   // floats per smem row

#define SMEM_BYTES (3 * 128 * PAD * 4)

__device__ int g_mask[NB_ * NB_];

__global__ void normalize_mask_kernel(const unsigned char* __restrict__ raw)
{
    __shared__ int mode;  // 0 = uint8 bool, 1 = int32, 2 = float32
    if (threadIdx.x == 0) {
        int pat_i32 = 1, pat_f32 = 1;
        // First 256 bytes = 64 words; readable under all candidate dtypes.
        for (int w = 0; w < 64; w++) {
            unsigned char b0 = raw[4 * w + 0];
            unsigned char b1 = raw[4 * w + 1];
            unsigned char b2 = raw[4 * w + 2];
            unsigned char b3 = raw[4 * w + 3];
            bool zero   = !(b0 | b1 | b2 | b3);
            bool i32one = (b0 == 1 && b1 == 0 && b2 == 0 && b3 == 0);
            bool f32one = (b0 == 0 && b1 == 0 && b2 == 0x80 && b3 == 0x3F);
            if (!(zero || i32one)) pat_i32 = 0;
            if (!(zero || f32one)) pat_f32 = 0;
        }
        mode = pat_i32 ? 1 : (pat_f32 ? 2 : 0);
    }
    __syncthreads();

    int idx = threadIdx.x;  // 0..255
    int val;
    if (mode == 1)      val = (((const int*)raw)[idx] != 0);
    else if (mode == 2) val = (((const float*)raw)[idx] != 0.0f);
    else                val = (raw[idx] != 0);
    g_mask[idx] = val;
}

__global__ __launch_bounds__(256, 1)
void bsattn_kernel(const float* __restrict__ q,
                   const float* __restrict__ k,
                   const float* __restrict__ v,
                   float* __restrict__ out)
{
    extern __shared__ float sm[];
    float* Qs  = sm;                  // [128][PAD]
    float* KVs = sm + 128 * PAD;      // [128][PAD] holds K_j, then V_j
    float* Ps  = sm + 2 * 128 * PAD;  // [128][PAD]

    const int i = blockIdx.x;   // query block
    const int h = blockIdx.y;
    const int b = blockIdx.z;
    const int tid = threadIdx.x;
    const int tx = tid & 15;    // 0..15 -> column lane
    const int ty = tid >> 4;    // 0..15 -> row group (8 rows each)

    const long base = ((long)(b * H_ + h)) * S_ * D_;
    const float* Qg = q + base + (long)i * BS_ * D_;

    // ---- load Q block (128x128 f32) into SMEM, coalesced float4 ----
    for (int t = tid; t < 128 * 32; t += 256) {
        int row = t >> 5;
        int c4  = (t & 31) << 2;
        float4 val = *(const float4*)(Qg + row * D_ + c4);
        float* dst = Qs + row * PAD + c4;
        dst[0] = val.x; dst[1] = val.y; dst[2] = val.z; dst[3] = val.w;
    }

    float o[8][8];
    #pragma unroll
    for (int r = 0; r < 8; r++)
        #pragma unroll
        for (int c = 0; c < 8; c++)
            o[r][c] = 0.0f;

    const float scale = 0.08838834764831845f;  // 1/sqrt(128)

    for (int j = 0; j < NB_; j++) {
        if (!g_mask[i * NB_ + j]) continue;   // uniform branch across CTA

        // previous iteration's PV reads of KVs/Ps must be complete
        __syncthreads();

        // ---- load K_j into KVs ----
        const float* Kg = k + base + (long)j * BS_ * D_;
        for (int t = tid; t < 128 * 32; t += 256) {
            int row = t >> 5;
            int c4  = (t & 31) << 2;
            float4 val = *(const float4*)(Kg + row * D_ + c4);
            float* dst = KVs + row * PAD + c4;
            dst[0] = val.x; dst[1] = val.y; dst[2] = val.z; dst[3] = val.w;
        }
        __syncthreads();

        // ---- S = Q K^T : rows 8*ty+r, cols tx+16*c ----
        float s[8][8];
        #pragma unroll
        for (int r = 0; r < 8; r++)
            #pragma unroll
            for (int c = 0; c < 8; c++)
                s[r][c] = 0.0f;

        #pragma unroll 2
        for (int d = 0; d < 128; d++) {
            float qr[8], kc[8];
            #pragma unroll
            for (int r = 0; r < 8; r++) qr[r] = Qs[(8 * ty + r) * PAD + d];
            #pragma unroll
            for (int c = 0; c < 8; c++) kc[c] = KVs[(tx + 16 * c) * PAD + d];
            #pragma unroll
            for (int r = 0; r < 8; r++)
                #pragma unroll
                for (int c = 0; c < 8; c++)
                    s[r][c] = fmaf(qr[r], kc[c], s[r][c]);
        }

        // ---- per-row softmax over 128 cols (16 lanes x 8 cols each) ----
        #pragma unroll
        for (int r = 0; r < 8; r++) {
            float mx = -1e30f;
            #pragma unroll
            for (int c = 0; c < 8; c++) {
                s[r][c] *= scale;
                mx = fmaxf(mx, s[r][c]);
            }
            #pragma unroll
            for (int off = 8; off >= 1; off >>= 1)
                mx = fmaxf(mx, __shfl_xor_sync(0xffffffffu, mx, off));
            float sum = 0.0f;
            #pragma unroll
            for (int c = 0; c < 8; c++) {
                s[r][c] = __expf(s[r][c] - mx);
                sum += s[r][c];
            }
            #pragma unroll
            for (int off = 8; off >= 1; off >>= 1)
                sum += __shfl_xor_sync(0xffffffffu, sum, off);
            float inv = 1.0f / sum;
            #pragma unroll
            for (int c = 0; c < 8; c++)
                s[r][c] *= inv;
        }

        // ---- store P to SMEM ----
        #pragma unroll
        for (int r = 0; r < 8; r++)
            #pragma unroll
            for (int c = 0; c < 8; c++)
                Ps[(8 * ty + r) * PAD + tx + 16 * c] = s[r][c];

        // all K reads + P writes done before KVs is overwritten with V
        __syncthreads();

        // ---- load V_j into KVs ----
        const float* Vg = v + base + (long)j * BS_ * D_;
        for (int t = tid; t < 128 * 32; t += 256) {
            int row = t >> 5;
            int c4  = (t & 31) << 2;
            float4 val = *(const float4*)(Vg + row * D_ + c4);
            float* dst = KVs + row * PAD + c4;
            dst[0] = val.x; dst[1] = val.y; dst[2] = val.z; dst[3] = val.w;
        }
        __syncthreads();

        // ---- O += P @ V : rows 8*ty+r, dcols tx+16*c ----
        #pragma unroll 2
        for (int kk = 0; kk < 128; kk++) {
            float pr[8], vc[8];
            #pragma unroll
            for (int r = 0; r < 8; r++) pr[r] = Ps[(8 * ty + r) * PAD + kk];
            #pragma unroll
            for (int c = 0; c < 8; c++) vc[c] = KVs[kk * PAD + tx + 16 * c];
            #pragma unroll
            for (int r = 0; r < 8; r++)
                #pragma unroll
                for (int c = 0; c < 8; c++)
                    o[r][c] = fmaf(pr[r], vc[c], o[r][c]);
        }
    }

    // ---- write output ----
    float* Og = out + base + (long)i * BS_ * D_;
    #pragma unroll
    for (int r = 0; r < 8; r++)
        #pragma unroll
        for (int c = 0; c < 8; c++)
            Og[(8 * ty + r) * D_ + tx + 16 * c] = o[r][c];
}

extern "C" void kernel_launch(void* const* d_in, const int* in_sizes, int n_in,
                              void* d_out, int out_size)
{
    const float* q = (const float*)d_in[0];
    const float* k = (const float*)d_in[1];
    const float* v = (const float*)d_in[2];
    const unsigned char* mask_raw = (const unsigned char*)d_in[3];
    float* out = (float*)d_out;

    normalize_mask_kernel<<<1, 256>>>(mask_raw);

    cudaFuncSetAttribute(bsattn_kernel,
                         cudaFuncAttributeMaxDynamicSharedMemorySize, SMEM_BYTES);

    dim3 grid(NB_, H_, B_);
    bsattn_kernel<<<grid, 256, SMEM_BYTES>>>(q, k, v, out);
}